// round 4
// baseline (speedup 1.0000x reference)
#include <cuda_runtime.h>
#include <math.h>

// out[i,j] = | prod_k cos((x[i,k] - y[j,k]) / 2) |
// cos((a-b)/2) = cos(a/2)cos(b/2) + sin(a/2)sin(b/2)
// Fused per-CTA __sincosf prologue -> pure f32x2-FMA mainloop, LDS.128 only.

typedef unsigned long long u64;

__device__ __forceinline__ u64 fma2(u64 a, u64 b, u64 c) {
    u64 d;
    asm("fma.rn.f32x2 %0, %1, %2, %3;" : "=l"(d) : "l"(a), "l"(b), "l"(c));
    return d;
}
__device__ __forceinline__ u64 mul2(u64 a, u64 b) {
    u64 d;
    asm("mul.rn.f32x2 %0, %1, %2;" : "=l"(d) : "l"(a), "l"(b));
    return d;
}
__device__ __forceinline__ u64 dup2(float x) {
    u64 d;
    asm("mov.b64 %0, {%1, %2};" : "=l"(d) : "f"(x), "f"(x));
    return d;
}

// 128x128 tile per CTA, 256 threads, 8x8 outputs/thread.
// Thread (tx,ty): j = j0 + 8*tx + {0..7}, i = i0 + 8*ty + {0..7}.
// Smem: s_xc/s_xs duplicated-pair u64 (16KB+16KB), s_yc/s_ys scalar (8KB+8KB) = 48KB.
__global__ __launch_bounds__(256, 2)
void qk_fused(const float* __restrict__ x, const float* __restrict__ y,
              float* __restrict__ out, int n, int m) {
    __shared__ __align__(16) u64   s_xc[16][128];  // [k][i] = (cos,cos) of x/2
    __shared__ __align__(16) u64   s_xs[16][128];  // [k][i] = (sin,sin)
    __shared__ __align__(16) float s_yc[16][128];  // [k][j] = cos(y/2)
    __shared__ __align__(16) float s_ys[16][128];  // [k][j] = sin(y/2)

    const int tid = threadIdx.x;
    const int i0 = blockIdx.y * 128;
    const int j0 = blockIdx.x * 128;

    // Prologue: r-fast mapping -> conflict-free smem stores (lanes = consecutive r).
    #pragma unroll
    for (int c = 0; c < 8; c++) {
        int e = tid + 256 * c;
        int r = e & 127, k = e >> 7;       // c=0..7 with 2 k's each -> k in 0..15
        float sx, cx;
        __sincosf(0.5f * x[(i0 + r) * 16 + k], &sx, &cx);
        s_xc[k][r] = dup2(cx);
        s_xs[k][r] = dup2(sx);
        float sy, cy;
        __sincosf(0.5f * y[(j0 + r) * 16 + k], &sy, &cy);
        s_yc[k][r] = cy;
        s_ys[k][r] = sy;
    }
    __syncthreads();

    const int tx = tid & 15;   // j block
    const int ty = tid >> 4;   // i block

    u64 acc[8][4];
    const u64 ONE2 = 0x3f8000003f800000ULL;
    #pragma unroll
    for (int ii = 0; ii < 8; ii++)
        #pragma unroll
        for (int p = 0; p < 4; p++) acc[ii][p] = ONE2;

    #pragma unroll 4
    for (int k = 0; k < 16; k++) {
        // y: 8 contiguous floats = 4 pairs, via 2x LDS.128 per array
        ulonglong2 a0 = *(const ulonglong2*)&s_yc[k][8 * tx];
        ulonglong2 a1 = *(const ulonglong2*)&s_yc[k][8 * tx + 4];
        ulonglong2 b0 = *(const ulonglong2*)&s_ys[k][8 * tx];
        ulonglong2 b1 = *(const ulonglong2*)&s_ys[k][8 * tx + 4];
        u64 yc[4] = {a0.x, a0.y, a1.x, a1.y};
        u64 ys[4] = {b0.x, b0.y, b1.x, b1.y};

        // x: 8 duplicated pairs per array, via 4x LDS.128 broadcast each
        u64 xc[8], xs[8];
        #pragma unroll
        for (int q = 0; q < 4; q++) {
            ulonglong2 xcq = *(const ulonglong2*)&s_xc[k][8 * ty + 2 * q];
            ulonglong2 xsq = *(const ulonglong2*)&s_xs[k][8 * ty + 2 * q];
            xc[2 * q] = xcq.x; xc[2 * q + 1] = xcq.y;
            xs[2 * q] = xsq.x; xs[2 * q + 1] = xsq.y;
        }

        #pragma unroll
        for (int ii = 0; ii < 8; ii++)
            #pragma unroll
            for (int p = 0; p < 4; p++)
                acc[ii][p] = mul2(acc[ii][p], fma2(xc[ii], yc[p], mul2(xs[ii], ys[p])));
    }

    // Epilogue: abs via mask, 2x STG.128 per row, fully coalesced.
    #pragma unroll
    for (int ii = 0; ii < 8; ii++) {
        int i = i0 + 8 * ty + ii;
        float* orow = out + (size_t)i * m + j0 + 8 * tx;
        ulonglong2 v0, v1;
        v0.x = acc[ii][0] & 0x7fffffff7fffffffULL;
        v0.y = acc[ii][1] & 0x7fffffff7fffffffULL;
        v1.x = acc[ii][2] & 0x7fffffff7fffffffULL;
        v1.y = acc[ii][3] & 0x7fffffff7fffffffULL;
        *(ulonglong2*)(orow)     = v0;
        *(ulonglong2*)(orow + 4) = v1;
    }
}

// Generic fallback for unexpected shapes.
__global__ void qk_naive(const float* __restrict__ x, const float* __restrict__ y,
                         float* __restrict__ out, int n, int m, int d) {
    int j = blockIdx.x * blockDim.x + threadIdx.x;
    int i = blockIdx.y;
    if (i >= n || j >= m) return;
    float p = 1.0f;
    for (int k = 0; k < d; k++)
        p *= cosf(0.5f * (x[i * d + k] - y[j * d + k]));
    out[(size_t)i * m + j] = fabsf(p);
}

extern "C" void kernel_launch(void* const* d_in, const int* in_sizes, int n_in,
                              void* d_out, int out_size) {
    const float* x = (const float*)d_in[0];
    const float* y = (const float*)d_in[1];
    float* out = (float*)d_out;

    long long sx = in_sizes[0], sy = in_sizes[1], so = out_size;
    int d = (int)llround(sqrt((double)sx * (double)sy / (double)so));
    if (d <= 0) d = 16;
    int n = (int)(sx / d);
    int m = (int)(sy / d);

    if (d == 16 && n % 128 == 0 && m % 128 == 0) {
        dim3 grid(m / 128, n / 128);
        qk_fused<<<grid, 256>>>(x, y, out, n, m);
    } else {
        qk_naive<<<dim3((m + 255) / 256, n), 256>>>(x, y, out, n, m, d);
    }
}

// round 5
// speedup vs baseline: 1.1347x; 1.1347x over previous
#include <cuda_runtime.h>
#include <math.h>

// out[i,j] = | prod_k cos((x[i,k] - y[j,k]) / 2) |
// cos((a-b)/2) = cos(a/2)cos(b/2) + sin(a/2)sin(b/2)
// Fused per-CTA __sincosf prologue -> R1-style pure f32x2-FMA mainloop (LDS.64).

typedef unsigned long long u64;

__device__ __forceinline__ u64 fma2(u64 a, u64 b, u64 c) {
    u64 d;
    asm("fma.rn.f32x2 %0, %1, %2, %3;" : "=l"(d) : "l"(a), "l"(b), "l"(c));
    return d;
}
__device__ __forceinline__ u64 mul2(u64 a, u64 b) {
    u64 d;
    asm("mul.rn.f32x2 %0, %1, %2;" : "=l"(d) : "l"(a), "l"(b));
    return d;
}
__device__ __forceinline__ u64 dup2(float x) {
    u64 d;
    asm("mov.b64 %0, {%1, %2};" : "=l"(d) : "f"(x), "f"(x));
    return d;
}

// 128x128 tile per CTA, 256 threads, 8x8 outputs/thread (as 8x4 f32x2 pairs).
// Smem: x as duplicated (v,v) u64 pairs (16KB+16KB), y scalar (8KB+8KB) = 48KB.
__global__ __launch_bounds__(256, 2)
void qk_fused(const float* __restrict__ x, const float* __restrict__ y,
              float* __restrict__ out, int n, int m) {
    __shared__ u64   s_xc[16][128];   // [k][i] = (cos,cos) of x/2
    __shared__ u64   s_xs[16][128];   // [k][i] = (sin,sin)
    __shared__ float s_yc[16][128];   // [k][j] = cos(y/2)
    __shared__ float s_ys[16][128];   // [k][j] = sin(y/2)

    const int tid = threadIdx.x;
    const int i0 = blockIdx.y * 128;
    const int j0 = blockIdx.x * 128;

    // Prologue: r-fast mapping -> conflict-free smem stores.
    #pragma unroll
    for (int c = 0; c < 8; c++) {
        int e = tid + 256 * c;
        int r = e & 127, k = e >> 7;       // k in 0..15
        float sx, cx;
        __sincosf(0.5f * x[(i0 + r) * 16 + k], &sx, &cx);
        s_xc[k][r] = dup2(cx);
        s_xs[k][r] = dup2(sx);
        float sy, cy;
        __sincosf(0.5f * y[(j0 + r) * 16 + k], &sy, &cy);
        s_yc[k][r] = cy;
        s_ys[k][r] = sy;
    }
    __syncthreads();

    const int tx = tid & 15;   // j dimension (16 threads)
    const int ty = tid >> 4;   // i dimension (16 threads)

    u64 acc[8][4];
    const u64 ONE2 = 0x3f8000003f800000ULL;  // (1.0f, 1.0f)
    #pragma unroll
    for (int ii = 0; ii < 8; ii++)
        #pragma unroll
        for (int jj = 0; jj < 4; jj++) acc[ii][jj] = ONE2;

    #pragma unroll 4
    for (int k = 0; k < 16; k++) {
        u64 yc[4], ys[4];
        #pragma unroll
        for (int jj = 0; jj < 4; jj++) {
            // j-pair (2*tx, 2*tx+1) + 32*jj : 8B-aligned, conflict-free across tx
            yc[jj] = *(const u64*)&s_yc[k][2 * tx + 32 * jj];
            ys[jj] = *(const u64*)&s_ys[k][2 * tx + 32 * jj];
        }
        #pragma unroll
        for (int ii = 0; ii < 8; ii++) {
            u64 xc = s_xc[k][ty + 16 * ii];   // LDS.64 broadcast (2 addrs/warp)
            u64 xs = s_xs[k][ty + 16 * ii];
            #pragma unroll
            for (int jj = 0; jj < 4; jj++) {
                u64 t = fma2(xc, yc[jj], mul2(xs, ys[jj]));
                acc[ii][jj] = mul2(acc[ii][jj], t);
            }
        }
    }

    // abs via bitmask, 8B vectorized stores (coalesced per half-warp)
    #pragma unroll
    for (int ii = 0; ii < 8; ii++) {
        int i = i0 + ty + 16 * ii;
        float* orow = out + (size_t)i * m + j0;
        #pragma unroll
        for (int jj = 0; jj < 4; jj++) {
            u64 a = acc[ii][jj] & 0x7fffffff7fffffffULL;
            *(u64*)&orow[2 * tx + 32 * jj] = a;
        }
    }
}

// Generic fallback for unexpected shapes.
__global__ void qk_naive(const float* __restrict__ x, const float* __restrict__ y,
                         float* __restrict__ out, int n, int m, int d) {
    int j = blockIdx.x * blockDim.x + threadIdx.x;
    int i = blockIdx.y;
    if (i >= n || j >= m) return;
    float p = 1.0f;
    for (int k = 0; k < d; k++)
        p *= cosf(0.5f * (x[i * d + k] - y[j * d + k]));
    out[(size_t)i * m + j] = fabsf(p);
}

extern "C" void kernel_launch(void* const* d_in, const int* in_sizes, int n_in,
                              void* d_out, int out_size) {
    const float* x = (const float*)d_in[0];
    const float* y = (const float*)d_in[1];
    float* out = (float*)d_out;

    long long sx = in_sizes[0], sy = in_sizes[1], so = out_size;
    int d = (int)llround(sqrt((double)sx * (double)sy / (double)so));
    if (d <= 0) d = 16;
    int n = (int)(sx / d);
    int m = (int)(sy / d);

    if (d == 16 && n % 128 == 0 && m % 128 == 0) {
        dim3 grid(m / 128, n / 128);
        qk_fused<<<grid, 256>>>(x, y, out, n, m);
    } else {
        qk_naive<<<dim3((m + 255) / 256, n), 256>>>(x, y, out, n, m, d);
    }
}